// round 2
// baseline (speedup 1.0000x reference)
#include <cuda_runtime.h>
#include <math.h>

#define BATCH 2
#define NCH   8
#define HI    256
#define HS    64
#define HW    4096   // 64*64
#define CDIM  256

// ---------------- scratch (static __device__, no allocations) ----------------
// side 0 = target, side 1 = source. g_featT normalized in place after k_mean.
__device__ float g_featT[2][BATCH][HW][CDIM];   // 16 MB
__device__ float g_col[2][BATCH][HW][3];
__device__ int   g_lab[2][BATCH][HW];
__device__ int   g_list[2][BATCH][NCH][HW];
__device__ int   g_cnt[2][BATCH][NCH];
__device__ float g_mean[2][BATCH][NCH][CDIM];
__device__ float g_canvas[BATCH][3][HW];

// ---------------- K1: labels (nearest), colors (bilinear down), zero canvas --
__global__ void k_pre(const float* __restrict__ toh, const float* __restrict__ soh,
                      const float* __restrict__ trgb, const float* __restrict__ srgb)
{
    int pix = blockIdx.x * blockDim.x + threadIdx.x;
    int b = blockIdx.y;
    if (pix >= HW) return;
    int y = pix >> 6, x = pix & 63;
    int y4 = y * 4, x4 = x * 4;

    // nearest-down label at (4y, 4x): floor(d*256/64) = 4d
    int tl = 0, sl = 0;
#pragma unroll
    for (int ch = 0; ch < NCH; ch++) {
        size_t o = ((size_t)(b * NCH + ch) * HI + y4) * HI + x4;
        if (toh[o] > 0.f) tl = ch;
        if (soh[o] > 0.f) sl = ch;
    }
    g_lab[0][b][pix] = tl;
    g_lab[1][b][pix] = sl;

    // bilinear downsample 256->64, half-pixel: src = 4d + 1.5 -> avg of 2x2 at (+1,+2)
#pragma unroll
    for (int ch = 0; ch < 3; ch++) {
        size_t base = ((size_t)(b * 3 + ch) * HI + (y4 + 1)) * HI + (x4 + 1);
        g_col[0][b][pix][ch] = 0.25f * (trgb[base] + trgb[base + 1] + trgb[base + HI] + trgb[base + HI + 1]);
        g_col[1][b][pix][ch] = 0.25f * (srgb[base] + srgb[base + 1] + srgb[base + HI] + srgb[base + HI + 1]);
    }
    g_canvas[b][0][pix] = 0.f;
    g_canvas[b][1][pix] = 0.f;
    g_canvas[b][2][pix] = 0.f;
}

// ---------------- K2: transpose features [b][ch][pix] -> [side][b][pix][ch] --
__global__ void k_transpose(const float* __restrict__ tfeat, const float* __restrict__ sfeat)
{
    __shared__ float tile[32][33];
    int side = blockIdx.z >> 1;
    int b    = blockIdx.z & 1;
    const float* in = side ? sfeat : tfeat;
    int pix0 = blockIdx.x * 32, ch0 = blockIdx.y * 32;
    int tx = threadIdx.x, ty = threadIdx.y;  // (32, 8)
#pragma unroll
    for (int i = 0; i < 32; i += 8)
        tile[ty + i][tx] = in[((size_t)(b * CDIM + ch0 + ty + i)) * HW + pix0 + tx];
    __syncthreads();
#pragma unroll
    for (int i = 0; i < 32; i += 8)
        g_featT[side][b][pix0 + ty + i][ch0 + tx] = tile[tx][ty + i];
}

// ---------------- K3: deterministic order-preserving per-class compaction ----
__global__ void k_compact()
{
    int id = blockIdx.x;               // [0,32): side*16 + b*8 + cls
    int cls = id & 7;
    int b   = (id >> 3) & 1;
    int side = id >> 4;
    int lane = threadIdx.x;
    int base = 0;
    for (int start = 0; start < HW; start += 32) {
        int p = start + lane;
        bool m = (g_lab[side][b][p] == cls);
        unsigned bal = __ballot_sync(0xffffffffu, m);
        if (m) g_list[side][b][cls][base + __popc(bal & ((1u << lane) - 1u))] = p;
        base += __popc(bal);
    }
    if (lane == 0) g_cnt[side][b][cls] = base;
}

// ---------------- K4: per-(side,b,class) masked channel means ----------------
__global__ void k_mean()
{
    int id = blockIdx.x;
    int cls = id & 7;
    int b   = (id >> 3) & 1;
    int side = id >> 4;
    int ch = threadIdx.x;
    int n = g_cnt[side][b][cls];
    const int* __restrict__ lst = g_list[side][b][cls];
    float s = 0.f;
    for (int i = 0; i < n; i++)
        s += g_featT[side][b][lst[i]][ch];
    g_mean[side][b][cls][ch] = s / (float)max(n, 1);
}

// ---------------- K5: center + per-pixel L2 normalize (in place) -------------
__global__ void k_norm()
{
    int pix = blockIdx.x, b = blockIdx.y, side = blockIdx.z;
    int lab = g_lab[side][b][pix];
    if (lab == 0) return;   // class-0 pixels never used
    int tid = threadIdx.x;
    float v = g_featT[side][b][pix][tid] - g_mean[side][b][lab][tid];
    float sq = v * v;
#pragma unroll
    for (int off = 16; off; off >>= 1) sq += __shfl_xor_sync(0xffffffffu, sq, off);
    __shared__ float ws[8];
    __shared__ float total;
    if ((tid & 31) == 0) ws[tid >> 5] = sq;
    __syncthreads();
    if (tid < 8) {
        float t = ws[tid];
#pragma unroll
        for (int off = 4; off; off >>= 1) t += __shfl_xor_sync(0xffu, t, off);
        if (tid == 0) total = t;
    }
    __syncthreads();
    int n = g_cnt[side][b][lab];
    float scale = (n == 1) ? 1.f : 1.f / fmaxf(sqrtf(total), 1e-12f);
    g_featT[side][b][pix][tid] = v * scale;
}

// ---------------- K6: fused masked attention + online softmax ----------------
#define TPB 16   // targets per block
#define CS  32   // source chunk in smem

__global__ void __launch_bounds__(256) k_attn()
{
    __shared__ float S[CS][CDIM];   // 32 KB source feature chunk
    __shared__ float SC[CS][4];     // source colors

    int cls = blockIdx.y + 1;       // classes 1..7
    int b   = blockIdx.z;
    int ntT = g_cnt[0][b][cls];
    int t0  = blockIdx.x * TPB;
    if (t0 >= ntT) return;

    int scnt = g_cnt[1][b][cls];
    int srcSide = (scnt < 9) ? 0 : 1;       // use_self branch
    int ns = g_cnt[srcSide][b][cls];
    const int* __restrict__ slist = g_list[srcSide][b][cls];

    int wid = threadIdx.x >> 5, lane = threadIdx.x & 31;
    // lane-channel mapping: conflict-free LDS.128 (lanes 0..7 cover words 0..31)
    int o1 = lane * 4, o2 = 128 + lane * 4;

    int ti0 = t0 + wid * 2, ti1 = ti0 + 1;
    bool act0 = ti0 < ntT, act1 = ti1 < ntT;
    int tp0 = act0 ? g_list[0][b][cls][ti0] : 0;
    int tp1 = act1 ? g_list[0][b][cls][ti1] : 0;

    float4 a0l = *(const float4*)&g_featT[0][b][tp0][o1];
    float4 a0h = *(const float4*)&g_featT[0][b][tp0][o2];
    float4 a1l = *(const float4*)&g_featT[0][b][tp1][o1];
    float4 a1h = *(const float4*)&g_featT[0][b][tp1][o2];

    float m0 = -1e30f, l0 = 0.f, x0 = 0.f, y0 = 0.f, z0 = 0.f;
    float m1 = -1e30f, l1 = 0.f, x1 = 0.f, y1 = 0.f, z1 = 0.f;

    for (int sc0 = 0; sc0 < ns; sc0 += CS) {
        int n = min(CS, ns - sc0);
        // cooperative load: warp w fills source vecs w*4 .. w*4+3
#pragma unroll
        for (int jj = 0; jj < 4; jj++) {
            int j = wid * 4 + jj;
            if (j < n) {
                int sp = slist[sc0 + j];
                *(float4*)&S[j][o1] = *(const float4*)&g_featT[srcSide][b][sp][o1];
                *(float4*)&S[j][o2] = *(const float4*)&g_featT[srcSide][b][sp][o2];
                if (lane < 3) SC[j][lane] = g_col[srcSide][b][sp][lane];
            }
        }
        __syncthreads();

        for (int j = 0; j < n; j++) {
            float4 ul = *(const float4*)&S[j][o1];
            float4 uh = *(const float4*)&S[j][o2];
            float d0 = a0l.x*ul.x + a0l.y*ul.y + a0l.z*ul.z + a0l.w*ul.w
                     + a0h.x*uh.x + a0h.y*uh.y + a0h.z*uh.z + a0h.w*uh.w;
            float d1 = a1l.x*ul.x + a1l.y*ul.y + a1l.z*ul.z + a1l.w*ul.w
                     + a1h.x*uh.x + a1h.y*uh.y + a1h.z*uh.z + a1h.w*uh.w;
#pragma unroll
            for (int off = 16; off; off >>= 1) {
                d0 += __shfl_xor_sync(0xffffffffu, d0, off);
                d1 += __shfl_xor_sync(0xffffffffu, d1, off);
            }
            float cx = SC[j][0], cy = SC[j][1], cz = SC[j][2];
            if (d0 <= m0) {            // common case: no max update, 1 exp
                float p = __expf(d0 - m0);
                l0 += p; x0 += p * cx; y0 += p * cy; z0 += p * cz;
            } else {
                float al = __expf(m0 - d0);
                l0 = l0 * al + 1.f; x0 = x0 * al + cx; y0 = y0 * al + cy; z0 = z0 * al + cz;
                m0 = d0;
            }
            if (d1 <= m1) {
                float p = __expf(d1 - m1);
                l1 += p; x1 += p * cx; y1 += p * cy; z1 += p * cz;
            } else {
                float al = __expf(m1 - d1);
                l1 = l1 * al + 1.f; x1 = x1 * al + cx; y1 = y1 * al + cy; z1 = z1 * al + cz;
                m1 = d1;
            }
        }
        __syncthreads();
    }

    if (lane == 0) {
        if (act0) {
            float inv = 1.f / l0;
            g_canvas[b][0][tp0] = x0 * inv;
            g_canvas[b][1][tp0] = y0 * inv;
            g_canvas[b][2][tp0] = z0 * inv;
        }
        if (act1) {
            float inv = 1.f / l1;
            g_canvas[b][0][tp1] = x1 * inv;
            g_canvas[b][1][tp1] = y1 * inv;
            g_canvas[b][2][tp1] = z1 * inv;
        }
    }
}

// ---------------- K7: bilinear 64->256 upsample + clip -----------------------
__global__ void k_up(float* __restrict__ out)
{
    int idx = blockIdx.x * blockDim.x + threadIdx.x;
    if (idx >= BATCH * 3 * HI * HI) return;
    int ox = idx & 255;
    int oy = (idx >> 8) & 255;
    int bc = idx >> 16;
    int c = bc % 3, b = bc / 3;
    float sy = oy * 0.25f - 0.375f;
    float sx = ox * 0.25f - 0.375f;
    int iy = (int)floorf(sy), ix = (int)floorf(sx);
    float wy = sy - (float)iy, wx = sx - (float)ix;
    int ya = max(iy, 0), yb = min(iy + 1, HS - 1);
    int xa = max(ix, 0), xb = min(ix + 1, HS - 1);
    const float* __restrict__ P = g_canvas[b][c];
    float v00 = P[ya * HS + xa], v01 = P[ya * HS + xb];
    float v10 = P[yb * HS + xa], v11 = P[yb * HS + xb];
    float v = (1.f - wy) * ((1.f - wx) * v00 + wx * v01)
            +        wy  * ((1.f - wx) * v10 + wx * v11);
    out[idx] = fminf(fmaxf(v, -1.f), 1.f);
}

// ---------------- launch -----------------------------------------------------
extern "C" void kernel_launch(void* const* d_in, const int* in_sizes, int n_in,
                              void* d_out, int out_size)
{
    const float* src_rgb = (const float*)d_in[0];
    const float* tgt_rgb = (const float*)d_in[1];
    const float* src_oh  = (const float*)d_in[2];
    const float* tgt_oh  = (const float*)d_in[3];
    const float* t_feat  = (const float*)d_in[4];
    const float* s_feat  = (const float*)d_in[5];
    float* out = (float*)d_out;

    k_pre<<<dim3(HW / 256, BATCH), 256>>>(tgt_oh, src_oh, tgt_rgb, src_rgb);
    k_transpose<<<dim3(HW / 32, CDIM / 32, 2 * BATCH), dim3(32, 8)>>>(t_feat, s_feat);
    k_compact<<<2 * BATCH * NCH, 32>>>();
    k_mean<<<2 * BATCH * NCH, 256>>>();
    k_norm<<<dim3(HW, BATCH, 2), 256>>>();
    k_attn<<<dim3(HW / TPB, NCH - 1, BATCH), 256>>>();
    k_up<<<(BATCH * 3 * HI * HI) / 256, 256>>>(out);
}

// round 3
// speedup vs baseline: 1.4005x; 1.4005x over previous
#include <cuda_runtime.h>
#include <math.h>

#define BATCH 2
#define NCH   8
#define HI    256
#define HS    64
#define HW    4096
#define CDIM  256
#define LOG2E 1.4426950408889634f

typedef unsigned long long ull;

// ---------------- scratch ----------------------------------------------------
__device__ float  g_featT[2][BATCH][HW][CDIM];   // raw transposed features
__device__ float4 g_colP[2][BATCH][HW];
__device__ int    g_lab[2][BATCH][HW];
__device__ int    g_list[2][BATCH][NCH][HW];
__device__ int    g_cnt[2][BATCH][NCH];
__device__ float  g_meanP[2][BATCH][NCH][16][CDIM];
__device__ float  g_mean[2][BATCH][NCH][CDIM];
__device__ float  g_scale[2][BATCH][HW];
__device__ float  g_canvas[BATCH][3][HW];

__device__ __forceinline__ void fma2(ull &d, ull a, ull b) {
    asm("fma.rn.f32x2 %0, %1, %2, %0;" : "+l"(d) : "l"(a), "l"(b));
}
__device__ __forceinline__ float2 unpk(ull v) {
    float2 r; asm("mov.b64 {%0,%1}, %2;" : "=f"(r.x), "=f"(r.y) : "l"(v)); return r;
}
__device__ __forceinline__ float ex2(float x) {
    float r; asm("ex2.approx.f32 %0, %1;" : "=f"(r) : "f"(x)); return r;
}

// ---------------- K1: labels, colors, zero canvas ----------------------------
__global__ void k_pre(const float* __restrict__ toh, const float* __restrict__ soh,
                      const float* __restrict__ trgb, const float* __restrict__ srgb)
{
    int pix = blockIdx.x * blockDim.x + threadIdx.x;
    int b = blockIdx.y;
    if (pix >= HW) return;
    int y = pix >> 6, x = pix & 63;
    int y4 = y * 4, x4 = x * 4;
    int tl = 0, sl = 0;
#pragma unroll
    for (int ch = 0; ch < NCH; ch++) {
        size_t o = ((size_t)(b * NCH + ch) * HI + y4) * HI + x4;
        if (toh[o] > 0.f) tl = ch;
        if (soh[o] > 0.f) sl = ch;
    }
    g_lab[0][b][pix] = tl;
    g_lab[1][b][pix] = sl;
    float tc[3], sc[3];
#pragma unroll
    for (int ch = 0; ch < 3; ch++) {
        size_t base = ((size_t)(b * 3 + ch) * HI + (y4 + 1)) * HI + (x4 + 1);
        tc[ch] = 0.25f * (trgb[base] + trgb[base + 1] + trgb[base + HI] + trgb[base + HI + 1]);
        sc[ch] = 0.25f * (srgb[base] + srgb[base + 1] + srgb[base + HI] + srgb[base + HI + 1]);
    }
    g_colP[0][b][pix] = make_float4(tc[0], tc[1], tc[2], 0.f);
    g_colP[1][b][pix] = make_float4(sc[0], sc[1], sc[2], 0.f);
    g_canvas[b][0][pix] = 0.f;
    g_canvas[b][1][pix] = 0.f;
    g_canvas[b][2][pix] = 0.f;
}

// ---------------- K2: transpose [b][ch][pix] -> [side][b][pix][ch] -----------
__global__ void k_transpose(const float* __restrict__ tfeat, const float* __restrict__ sfeat)
{
    __shared__ float tile[32][33];
    int side = blockIdx.z >> 1;
    int b    = blockIdx.z & 1;
    const float* in = side ? sfeat : tfeat;
    int pix0 = blockIdx.x * 32, ch0 = blockIdx.y * 32;
    int tx = threadIdx.x, ty = threadIdx.y;  // (32, 8)
#pragma unroll
    for (int i = 0; i < 32; i += 8)
        tile[ty + i][tx] = in[((size_t)(b * CDIM + ch0 + ty + i)) * HW + pix0 + tx];
    __syncthreads();
#pragma unroll
    for (int i = 0; i < 32; i += 8)
        g_featT[side][b][pix0 + ty + i][ch0 + tx] = tile[tx][ty + i];
}

// ---------------- K3: per-class compaction (order-preserving) ----------------
__global__ void k_compact()
{
    int id = blockIdx.x;              // side*16 + b*8 + cls
    int cls = id & 7, b = (id >> 3) & 1, side = id >> 4;
    int lane = threadIdx.x;
    const int4* __restrict__ lp = (const int4*)g_lab[side][b];
    int* __restrict__ lst = g_list[side][b][cls];
    int base = 0;
    for (int r = 0; r < HW / 128; r++) {
        int4 v = lp[r * 32 + lane];
        int vv[4] = {v.x, v.y, v.z, v.w};
#pragma unroll
        for (int e = 0; e < 4; e++) {
            bool m = (vv[e] == cls);
            unsigned bal = __ballot_sync(0xffffffffu, m);
            if (m) lst[base + __popc(bal & ((1u << lane) - 1u))] = (r * 32 + lane) * 4 + e;
            base += __popc(bal);
        }
    }
    if (lane == 0) g_cnt[side][b][cls] = base;
}

// ---------------- K4a/K4b: class channel means (two-stage) -------------------
__global__ void k_meanA()
{
    int sbc = blockIdx.x;
    int cls = sbc & 7, b = (sbc >> 3) & 1, side = sbc >> 4;
    int ck = blockIdx.y, ch = threadIdx.x;
    int n = g_cnt[side][b][cls];
    int lo = (n * ck) >> 4, hi = (n * (ck + 1)) >> 4;
    const int* __restrict__ lst = g_list[side][b][cls];
    float s = 0.f;
    for (int i = lo; i < hi; i++)
        s += g_featT[side][b][lst[i]][ch];
    g_meanP[side][b][cls][ck][ch] = s;
}

__global__ void k_meanB()
{
    int sbc = blockIdx.x;
    int cls = sbc & 7, b = (sbc >> 3) & 1, side = sbc >> 4;
    int ch = threadIdx.x;
    int n = g_cnt[side][b][cls];
    float s = 0.f;
#pragma unroll
    for (int ck = 0; ck < 16; ck++)
        s += g_meanP[side][b][cls][ck][ch];
    g_mean[side][b][cls][ch] = s / (float)max(n, 1);
}

// ---------------- K5: per-pixel 1/||f - mean|| -------------------------------
__global__ void k_scale()
{
    int pix = blockIdx.x, b = blockIdx.y, side = blockIdx.z;
    int lab = g_lab[side][b][pix];
    if (lab == 0) return;
    int tid = threadIdx.x;
    float v = g_featT[side][b][pix][tid] - g_mean[side][b][lab][tid];
    float sq = v * v;
#pragma unroll
    for (int off = 16; off; off >>= 1) sq += __shfl_xor_sync(0xffffffffu, sq, off);
    __shared__ float ws[8];
    if ((tid & 31) == 0) ws[tid >> 5] = sq;
    __syncthreads();
    if (tid == 0) {
        float t = 0.f;
#pragma unroll
        for (int w = 0; w < 8; w++) t += ws[w];
        int n = g_cnt[side][b][lab];
        g_scale[side][b][pix] = (n == 1) ? 1.f : 1.f / fmaxf(sqrtf(t), 1e-12f);
    }
}

// ---------------- K6: fused attention (register-tiled) -----------------------
// 8 warps; warp g: targets 4g..4g+3, lane = source slot. No max-tracking:
// scores bounded by 1 (normalized vectors), log2e folded into target scale.
#define TGT 32
#define ST_BYTES (128 * 33 * 8)
#define TT_BYTES (128 * 34 * 8)
#define ATTN_SMEM (ST_BYTES + TT_BYTES + 2048)

__global__ void __launch_bounds__(256) k_attn()
{
    extern __shared__ unsigned char smem_raw[];
    float2 (*ST)[33] = (float2(*)[33])(smem_raw);
    float2 (*TT)[34] = (float2(*)[34])(smem_raw + ST_BYTES);
    float* MEANS = (float*)(smem_raw + ST_BYTES + TT_BYTES);
    float* MEANT = MEANS + 256;

    int cls = blockIdx.y + 1, b = blockIdx.z;
    int nt = g_cnt[0][b][cls];
    int t0 = blockIdx.x * TGT;
    if (t0 >= nt) return;

    int scnt = g_cnt[1][b][cls];
    int srcSide = (scnt < 9) ? 0 : 1;        // use_self branch
    int ns = g_cnt[srcSide][b][cls];
    const int* __restrict__ slist = g_list[srcSide][b][cls];
    const int* __restrict__ tlist = g_list[0][b][cls];

    int tid = threadIdx.x, g = tid >> 5, lane = tid & 31;

    MEANS[tid] = g_mean[srcSide][b][cls][tid];
    MEANT[tid] = g_mean[0][b][cls][tid];
    __syncthreads();

    // ---- fill TT: 32 targets, normalized, log2e folded ----------------------
    {
        int i = tid >> 3, p = tid & 7;       // 8 threads per target
        int ti = t0 + i;
        bool valid = ti < nt;
        int tp = tlist[valid ? ti : nt - 1];
        float sc = valid ? g_scale[0][b][tp] * LOG2E : 0.f;
        const float4* __restrict__ row = (const float4*)g_featT[0][b][tp];
        const float4* __restrict__ mr = (const float4*)MEANT;
#pragma unroll
        for (int r = 0; r < 8; r++) {
            int q = p + 8 * r;
            float4 f = row[q], m = mr[q];
            TT[2 * q][i]     = make_float2((f.x - m.x) * sc, (f.y - m.y) * sc);
            TT[2 * q + 1][i] = make_float2((f.z - m.z) * sc, (f.w - m.w) * sc);
        }
    }

    float lv0 = 0.f, lv1 = 0.f, lv2 = 0.f, lv3 = 0.f;
    float xv0 = 0.f, xv1 = 0.f, xv2 = 0.f, xv3 = 0.f;
    float yv0 = 0.f, yv1 = 0.f, yv2 = 0.f, yv3 = 0.f;
    float zv0 = 0.f, zv1 = 0.f, zv2 = 0.f, zv3 = 0.f;

    for (int c0 = 0; c0 < ns; c0 += 32) {
        int n = min(32, ns - c0);
        __syncthreads();                     // TT ready / prev chunk consumed
        {   // fill ST: 32 sources, normalized
            int j = tid >> 3, p = tid & 7;
            if (j < n) {
                int sp = slist[c0 + j];
                float sc = g_scale[srcSide][b][sp];
                const float4* __restrict__ row = (const float4*)g_featT[srcSide][b][sp];
                const float4* __restrict__ mr = (const float4*)MEANS;
#pragma unroll
                for (int r = 0; r < 8; r++) {
                    int q = p + 8 * r;
                    float4 f = row[q], m = mr[q];
                    ST[2 * q][j]     = make_float2((f.x - m.x) * sc, (f.y - m.y) * sc);
                    ST[2 * q + 1][j] = make_float2((f.z - m.z) * sc, (f.w - m.w) * sc);
                }
            }
        }
        __syncthreads();

        bool on = lane < n;
        float4 scol = on ? g_colP[srcSide][b][slist[c0 + lane]]
                         : make_float4(0.f, 0.f, 0.f, 0.f);

        ull d0 = 0, d1 = 0, d2 = 0, d3 = 0;
#pragma unroll 8
        for (int k2 = 0; k2 < 128; k2++) {
            ull s = *(const ull*)&ST[k2][lane];
            ulonglong2 ta = *(const ulonglong2*)&TT[k2][4 * g];
            ulonglong2 tb = *(const ulonglong2*)&TT[k2][4 * g + 2];
            fma2(d0, s, ta.x);
            fma2(d1, s, ta.y);
            fma2(d2, s, tb.x);
            fma2(d3, s, tb.y);
        }
        float2 e0 = unpk(d0), e1 = unpk(d1), e2 = unpk(d2), e3 = unpk(d3);
        float p0 = on ? ex2(e0.x + e0.y) : 0.f;
        float p1 = on ? ex2(e1.x + e1.y) : 0.f;
        float p2 = on ? ex2(e2.x + e2.y) : 0.f;
        float p3 = on ? ex2(e3.x + e3.y) : 0.f;
        lv0 += p0; xv0 += p0 * scol.x; yv0 += p0 * scol.y; zv0 += p0 * scol.z;
        lv1 += p1; xv1 += p1 * scol.x; yv1 += p1 * scol.y; zv1 += p1 * scol.z;
        lv2 += p2; xv2 += p2 * scol.x; yv2 += p2 * scol.y; zv2 += p2 * scol.z;
        lv3 += p3; xv3 += p3 * scol.x; yv3 += p3 * scol.y; zv3 += p3 * scol.z;
    }

    // final per-warp reduce + write
    float L[4] = {lv0, lv1, lv2, lv3};
    float X[4] = {xv0, xv1, xv2, xv3};
    float Y[4] = {yv0, yv1, yv2, yv3};
    float Z[4] = {zv0, zv1, zv2, zv3};
#pragma unroll
    for (int t = 0; t < 4; t++) {
        float l = L[t], x = X[t], y = Y[t], z = Z[t];
#pragma unroll
        for (int off = 16; off; off >>= 1) {
            l += __shfl_xor_sync(0xffffffffu, l, off);
            x += __shfl_xor_sync(0xffffffffu, x, off);
            y += __shfl_xor_sync(0xffffffffu, y, off);
            z += __shfl_xor_sync(0xffffffffu, z, off);
        }
        int ti = t0 + 4 * g + t;
        if (lane == 0 && ti < nt) {
            int tp = tlist[ti];
            float inv = 1.f / l;
            g_canvas[b][0][tp] = x * inv;
            g_canvas[b][1][tp] = y * inv;
            g_canvas[b][2][tp] = z * inv;
        }
    }
}

// ---------------- K7: bilinear 64->256 upsample + clip -----------------------
__global__ void k_up(float* __restrict__ out)
{
    int idx = blockIdx.x * blockDim.x + threadIdx.x;
    if (idx >= BATCH * 3 * HI * HI) return;
    int ox = idx & 255;
    int oy = (idx >> 8) & 255;
    int bc = idx >> 16;
    int c = bc % 3, b = bc / 3;
    float sy = oy * 0.25f - 0.375f;
    float sx = ox * 0.25f - 0.375f;
    int iy = (int)floorf(sy), ix = (int)floorf(sx);
    float wy = sy - (float)iy, wx = sx - (float)ix;
    int ya = max(iy, 0), yb = min(iy + 1, HS - 1);
    int xa = max(ix, 0), xb = min(ix + 1, HS - 1);
    const float* __restrict__ P = g_canvas[b][c];
    float v00 = P[ya * HS + xa], v01 = P[ya * HS + xb];
    float v10 = P[yb * HS + xa], v11 = P[yb * HS + xb];
    float v = (1.f - wy) * ((1.f - wx) * v00 + wx * v01)
            +        wy  * ((1.f - wx) * v10 + wx * v11);
    out[idx] = fminf(fmaxf(v, -1.f), 1.f);
}

// ---------------- launch -----------------------------------------------------
extern "C" void kernel_launch(void* const* d_in, const int* in_sizes, int n_in,
                              void* d_out, int out_size)
{
    const float* src_rgb = (const float*)d_in[0];
    const float* tgt_rgb = (const float*)d_in[1];
    const float* src_oh  = (const float*)d_in[2];
    const float* tgt_oh  = (const float*)d_in[3];
    const float* t_feat  = (const float*)d_in[4];
    const float* s_feat  = (const float*)d_in[5];
    float* out = (float*)d_out;

    cudaFuncSetAttribute(k_attn, cudaFuncAttributeMaxDynamicSharedMemorySize, ATTN_SMEM);

    k_pre<<<dim3(HW / 256, BATCH), 256>>>(tgt_oh, src_oh, tgt_rgb, src_rgb);
    k_transpose<<<dim3(HW / 32, CDIM / 32, 2 * BATCH), dim3(32, 8)>>>(t_feat, s_feat);
    k_compact<<<2 * BATCH * NCH, 32>>>();
    k_meanA<<<dim3(2 * BATCH * NCH, 16), 256>>>();
    k_meanB<<<2 * BATCH * NCH, 256>>>();
    k_scale<<<dim3(HW, BATCH, 2), 256>>>();
    k_attn<<<dim3(HW / TGT, NCH - 1, BATCH), 256, ATTN_SMEM>>>();
    k_up<<<(BATCH * 3 * HI * HI) / 256, 256>>>(out);
}

// round 4
// speedup vs baseline: 1.9655x; 1.4034x over previous
#include <cuda_runtime.h>
#include <math.h>

#define BATCH 2
#define NCH   8
#define HI    256
#define HS    64
#define HW    4096
#define CDIM  256
#define LOG2E 1.4426950408889634f

typedef unsigned long long ull;

// ---------------- scratch ----------------------------------------------------
__device__ float  g_featT[2][BATCH][HW][CDIM];   // raw transposed features
__device__ float4 g_colP[2][BATCH][HW];
__device__ int    g_lab[2][BATCH][HW];
__device__ int    g_list[2][BATCH][NCH][HW];
__device__ int    g_cnt[2][BATCH][NCH];
__device__ float  g_meanP[2][BATCH][NCH][32][CDIM];
__device__ float  g_mean[2][BATCH][NCH][CDIM];
__device__ float  g_scale[2][BATCH][HW];
__device__ float4 g_part[2][BATCH][NCH][HW];     // per-half (x,y,z,l) partials
__device__ float  g_canvas[BATCH][3][HW];

__device__ __forceinline__ void fma2(ull &d, ull a, ull b) {
    asm("fma.rn.f32x2 %0, %1, %2, %0;" : "+l"(d) : "l"(a), "l"(b));
}
__device__ __forceinline__ float2 unpk(ull v) {
    float2 r; asm("mov.b64 {%0,%1}, %2;" : "=f"(r.x), "=f"(r.y) : "l"(v)); return r;
}
__device__ __forceinline__ float ex2(float x) {
    float r; asm("ex2.approx.f32 %0, %1;" : "=f"(r) : "f"(x)); return r;
}

// ---------------- K1: labels, colors, zero canvas ----------------------------
__global__ void k_pre(const float* __restrict__ toh, const float* __restrict__ soh,
                      const float* __restrict__ trgb, const float* __restrict__ srgb)
{
    int pix = blockIdx.x * blockDim.x + threadIdx.x;
    int b = blockIdx.y;
    if (pix >= HW) return;
    int y = pix >> 6, x = pix & 63;
    int y4 = y * 4, x4 = x * 4;
    int tl = 0, sl = 0;
#pragma unroll
    for (int ch = 0; ch < NCH; ch++) {
        size_t o = ((size_t)(b * NCH + ch) * HI + y4) * HI + x4;
        if (toh[o] > 0.f) tl = ch;
        if (soh[o] > 0.f) sl = ch;
    }
    g_lab[0][b][pix] = tl;
    g_lab[1][b][pix] = sl;
    float tc[3], sc[3];
#pragma unroll
    for (int ch = 0; ch < 3; ch++) {
        size_t base = ((size_t)(b * 3 + ch) * HI + (y4 + 1)) * HI + (x4 + 1);
        tc[ch] = 0.25f * (trgb[base] + trgb[base + 1] + trgb[base + HI] + trgb[base + HI + 1]);
        sc[ch] = 0.25f * (srgb[base] + srgb[base + 1] + srgb[base + HI] + srgb[base + HI + 1]);
    }
    g_colP[0][b][pix] = make_float4(tc[0], tc[1], tc[2], 0.f);
    g_colP[1][b][pix] = make_float4(sc[0], sc[1], sc[2], 0.f);
    g_canvas[b][0][pix] = 0.f;
    g_canvas[b][1][pix] = 0.f;
    g_canvas[b][2][pix] = 0.f;
}

// ---------------- K2: transpose [b][ch][pix] -> [side][b][pix][ch] -----------
__global__ void k_transpose(const float* __restrict__ tfeat, const float* __restrict__ sfeat)
{
    __shared__ float tile[32][33];
    int side = blockIdx.z >> 1;
    int b    = blockIdx.z & 1;
    const float* in = side ? sfeat : tfeat;
    int pix0 = blockIdx.x * 32, ch0 = blockIdx.y * 32;
    int tx = threadIdx.x, ty = threadIdx.y;  // (32, 8)
#pragma unroll
    for (int i = 0; i < 32; i += 8)
        tile[ty + i][tx] = in[((size_t)(b * CDIM + ch0 + ty + i)) * HW + pix0 + tx];
    __syncthreads();
#pragma unroll
    for (int i = 0; i < 32; i += 8)
        g_featT[side][b][pix0 + ty + i][ch0 + tx] = tile[tx][ty + i];
}

// ---------------- K3: per-class compaction (order-preserving) ----------------
__global__ void k_compact()
{
    int id = blockIdx.x;              // side*16 + b*8 + cls
    int cls = id & 7, b = (id >> 3) & 1, side = id >> 4;
    int lane = threadIdx.x;
    const int4* __restrict__ lp = (const int4*)g_lab[side][b];
    int* __restrict__ lst = g_list[side][b][cls];
    int base = 0;
    for (int r = 0; r < HW / 128; r++) {
        int4 v = lp[r * 32 + lane];
        int vv[4] = {v.x, v.y, v.z, v.w};
#pragma unroll
        for (int e = 0; e < 4; e++) {
            bool m = (vv[e] == cls);
            unsigned bal = __ballot_sync(0xffffffffu, m);
            if (m) lst[base + __popc(bal & ((1u << lane) - 1u))] = (r * 32 + lane) * 4 + e;
            base += __popc(bal);
        }
    }
    if (lane == 0) g_cnt[side][b][cls] = base;
}

// ---------------- K4a/K4b: class channel means (two-stage, 32 chunks) --------
__global__ void k_meanA()
{
    int sbc = blockIdx.x;
    int cls = sbc & 7, b = (sbc >> 3) & 1, side = sbc >> 4;
    int ck = blockIdx.y, ch = threadIdx.x;
    int n = g_cnt[side][b][cls];
    int lo = (n * ck) >> 5, hi = (n * (ck + 1)) >> 5;
    const int* __restrict__ lst = g_list[side][b][cls];
    float s = 0.f;
    for (int i = lo; i < hi; i++)
        s += g_featT[side][b][lst[i]][ch];
    g_meanP[side][b][cls][ck][ch] = s;
}

__global__ void k_meanB()
{
    int sbc = blockIdx.x;
    int cls = sbc & 7, b = (sbc >> 3) & 1, side = sbc >> 4;
    int ch = threadIdx.x;
    int n = g_cnt[side][b][cls];
    float s = 0.f;
#pragma unroll
    for (int ck = 0; ck < 32; ck++)
        s += g_meanP[side][b][cls][ck][ch];
    g_mean[side][b][cls][ch] = s / (float)max(n, 1);
}

// ---------------- K5: per-pixel 1/||f - mean||  (warp per pixel) -------------
__global__ void k_scale()
{
    int warp = threadIdx.x >> 5, lane = threadIdx.x & 31;
    int pix = blockIdx.x * 8 + warp;
    int b = blockIdx.y, side = blockIdx.z;
    int lab = g_lab[side][b][pix];
    if (lab == 0) return;
    const float4* __restrict__ row = (const float4*)g_featT[side][b][pix];
    const float4* __restrict__ mr  = (const float4*)g_mean[side][b][lab];
    float sq = 0.f;
#pragma unroll
    for (int r = 0; r < 2; r++) {
        int q = lane + 32 * r;
        float4 f = row[q], m = mr[q];
        float ax = f.x - m.x, ay = f.y - m.y, az = f.z - m.z, aw = f.w - m.w;
        sq += ax * ax + ay * ay + az * az + aw * aw;
    }
#pragma unroll
    for (int off = 16; off; off >>= 1) sq += __shfl_xor_sync(0xffffffffu, sq, off);
    if (lane == 0) {
        int n = g_cnt[side][b][lab];
        g_scale[side][b][pix] = (n == 1) ? 1.f : 1.f / fmaxf(sqrtf(sq), 1e-12f);
    }
}

// ---------------- K6: attention (register-tiled, 2-way source split) ---------
// Block: 8 warps; warp g: targets 4g..4g+3, lane = source slot.
// blockIdx.z = b*2 + half; each half covers its range of sources, writes
// exact partial sums (x,y,z,l) to g_part; k_fin combines.
#define TGT 32
#define ST_BYTES (64 * 33 * 16)
#define TT_BYTES (64 * 33 * 16)
#define ATTN_SMEM (ST_BYTES + TT_BYTES + 2048)

__global__ void __launch_bounds__(256) k_attn()
{
    extern __shared__ unsigned char smem_raw[];
    float4 (*ST4)[33] = (float4(*)[33])(smem_raw);
    float4 (*TT4)[33] = (float4(*)[33])(smem_raw + ST_BYTES);
    float* MEANS = (float*)(smem_raw + ST_BYTES + TT_BYTES);
    float* MEANT = MEANS + 256;

    int cls  = blockIdx.y + 1;
    int half = blockIdx.z & 1;
    int b    = blockIdx.z >> 1;
    int nt = g_cnt[0][b][cls];
    int t0 = blockIdx.x * TGT;
    if (t0 >= nt) return;

    int scnt = g_cnt[1][b][cls];
    int srcSide = (scnt < 9) ? 0 : 1;        // use_self branch
    int nsAll = g_cnt[srcSide][b][cls];
    int sLo = (nsAll * half) >> 1;
    int sHi = (nsAll * (half + 1)) >> 1;
    const int* __restrict__ slist = g_list[srcSide][b][cls];
    const int* __restrict__ tlist = g_list[0][b][cls];

    int tid = threadIdx.x, g = tid >> 5, lane = tid & 31;

    MEANS[tid] = g_mean[srcSide][b][cls][tid];
    MEANT[tid] = g_mean[0][b][cls][tid];
    __syncthreads();

    // ---- fill TT4: 32 targets, normalized, log2e folded ---------------------
    {
        int i = tid >> 3, p = tid & 7;       // 8 threads per target
        int ti = t0 + i;
        bool valid = ti < nt;
        int tp = tlist[valid ? ti : nt - 1];
        float sc = valid ? g_scale[0][b][tp] * LOG2E : 0.f;
        const float4* __restrict__ row = (const float4*)g_featT[0][b][tp];
        const float4* __restrict__ mr = (const float4*)MEANT;
#pragma unroll
        for (int r = 0; r < 8; r++) {
            int q = p + 8 * r;               // k4 index
            float4 f = row[q], m = mr[q];
            TT4[q][i] = make_float4((f.x - m.x) * sc, (f.y - m.y) * sc,
                                    (f.z - m.z) * sc, (f.w - m.w) * sc);
        }
    }

    float lv0 = 0.f, lv1 = 0.f, lv2 = 0.f, lv3 = 0.f;
    float xv0 = 0.f, xv1 = 0.f, xv2 = 0.f, xv3 = 0.f;
    float yv0 = 0.f, yv1 = 0.f, yv2 = 0.f, yv3 = 0.f;
    float zv0 = 0.f, zv1 = 0.f, zv2 = 0.f, zv3 = 0.f;

    for (int c0 = sLo; c0 < sHi; c0 += 32) {
        int n = min(32, sHi - c0);
        __syncthreads();                     // TT ready / prev chunk consumed
        {   // fill ST4: 32 sources, normalized
            int j = tid >> 3, p = tid & 7;
            if (j < n) {
                int sp = slist[c0 + j];
                float sc = g_scale[srcSide][b][sp];
                const float4* __restrict__ row = (const float4*)g_featT[srcSide][b][sp];
                const float4* __restrict__ mr = (const float4*)MEANS;
#pragma unroll
                for (int r = 0; r < 8; r++) {
                    int q = p + 8 * r;
                    float4 f = row[q], m = mr[q];
                    ST4[q][j] = make_float4((f.x - m.x) * sc, (f.y - m.y) * sc,
                                            (f.z - m.z) * sc, (f.w - m.w) * sc);
                }
            }
        }
        __syncthreads();

        bool on = lane < n;
        float4 scol = on ? g_colP[srcSide][b][slist[c0 + lane]]
                         : make_float4(0.f, 0.f, 0.f, 0.f);

        ull d0 = 0, d1 = 0, d2 = 0, d3 = 0;
#pragma unroll 8
        for (int k4 = 0; k4 < 64; k4++) {
            ulonglong2 s  = *(const ulonglong2*)&ST4[k4][lane];
            ulonglong2 t0v = *(const ulonglong2*)&TT4[k4][4 * g];
            ulonglong2 t1v = *(const ulonglong2*)&TT4[k4][4 * g + 1];
            ulonglong2 t2v = *(const ulonglong2*)&TT4[k4][4 * g + 2];
            ulonglong2 t3v = *(const ulonglong2*)&TT4[k4][4 * g + 3];
            fma2(d0, s.x, t0v.x); fma2(d0, s.y, t0v.y);
            fma2(d1, s.x, t1v.x); fma2(d1, s.y, t1v.y);
            fma2(d2, s.x, t2v.x); fma2(d2, s.y, t2v.y);
            fma2(d3, s.x, t3v.x); fma2(d3, s.y, t3v.y);
        }
        float2 e0 = unpk(d0), e1 = unpk(d1), e2 = unpk(d2), e3 = unpk(d3);
        float p0 = on ? ex2(e0.x + e0.y) : 0.f;
        float p1 = on ? ex2(e1.x + e1.y) : 0.f;
        float p2 = on ? ex2(e2.x + e2.y) : 0.f;
        float p3 = on ? ex2(e3.x + e3.y) : 0.f;
        lv0 += p0; xv0 += p0 * scol.x; yv0 += p0 * scol.y; zv0 += p0 * scol.z;
        lv1 += p1; xv1 += p1 * scol.x; yv1 += p1 * scol.y; zv1 += p1 * scol.z;
        lv2 += p2; xv2 += p2 * scol.x; yv2 += p2 * scol.y; zv2 += p2 * scol.z;
        lv3 += p3; xv3 += p3 * scol.x; yv3 += p3 * scol.y; zv3 += p3 * scol.z;
    }

    float L[4] = {lv0, lv1, lv2, lv3};
    float X[4] = {xv0, xv1, xv2, xv3};
    float Y[4] = {yv0, yv1, yv2, yv3};
    float Z[4] = {zv0, zv1, zv2, zv3};
#pragma unroll
    for (int t = 0; t < 4; t++) {
        float l = L[t], x = X[t], y = Y[t], z = Z[t];
#pragma unroll
        for (int off = 16; off; off >>= 1) {
            l += __shfl_xor_sync(0xffffffffu, l, off);
            x += __shfl_xor_sync(0xffffffffu, x, off);
            y += __shfl_xor_sync(0xffffffffu, y, off);
            z += __shfl_xor_sync(0xffffffffu, z, off);
        }
        int ti = t0 + 4 * g + t;
        if (lane == 0 && ti < nt)
            g_part[half][b][cls][ti] = make_float4(x, y, z, l);
    }
}

// ---------------- K6b: combine partials, divide, scatter to canvas -----------
__global__ void k_fin()
{
    int cls = blockIdx.y + 1, b = blockIdx.z;
    int ti = blockIdx.x * blockDim.x + threadIdx.x;
    int nt = g_cnt[0][b][cls];
    if (ti >= nt) return;
    float4 pa = g_part[0][b][cls][ti];
    float4 pb = g_part[1][b][cls][ti];
    float l = pa.w + pb.w;
    float inv = 1.f / l;
    int tp = g_list[0][b][cls][ti];
    g_canvas[b][0][tp] = (pa.x + pb.x) * inv;
    g_canvas[b][1][tp] = (pa.y + pb.y) * inv;
    g_canvas[b][2][tp] = (pa.z + pb.z) * inv;
}

// ---------------- K7: bilinear 64->256 upsample + clip -----------------------
__global__ void k_up(float* __restrict__ out)
{
    int idx = blockIdx.x * blockDim.x + threadIdx.x;
    if (idx >= BATCH * 3 * HI * HI) return;
    int ox = idx & 255;
    int oy = (idx >> 8) & 255;
    int bc = idx >> 16;
    int c = bc % 3, b = bc / 3;
    float sy = oy * 0.25f - 0.375f;
    float sx = ox * 0.25f - 0.375f;
    int iy = (int)floorf(sy), ix = (int)floorf(sx);
    float wy = sy - (float)iy, wx = sx - (float)ix;
    int ya = max(iy, 0), yb = min(iy + 1, HS - 1);
    int xa = max(ix, 0), xb = min(ix + 1, HS - 1);
    const float* __restrict__ P = g_canvas[b][c];
    float v00 = P[ya * HS + xa], v01 = P[ya * HS + xb];
    float v10 = P[yb * HS + xa], v11 = P[yb * HS + xb];
    float v = (1.f - wy) * ((1.f - wx) * v00 + wx * v01)
            +        wy  * ((1.f - wx) * v10 + wx * v11);
    out[idx] = fminf(fmaxf(v, -1.f), 1.f);
}

// ---------------- launch -----------------------------------------------------
extern "C" void kernel_launch(void* const* d_in, const int* in_sizes, int n_in,
                              void* d_out, int out_size)
{
    const float* src_rgb = (const float*)d_in[0];
    const float* tgt_rgb = (const float*)d_in[1];
    const float* src_oh  = (const float*)d_in[2];
    const float* tgt_oh  = (const float*)d_in[3];
    const float* t_feat  = (const float*)d_in[4];
    const float* s_feat  = (const float*)d_in[5];
    float* out = (float*)d_out;

    cudaFuncSetAttribute(k_attn, cudaFuncAttributeMaxDynamicSharedMemorySize, ATTN_SMEM);

    k_pre<<<dim3(HW / 256, BATCH), 256>>>(tgt_oh, src_oh, tgt_rgb, src_rgb);
    k_transpose<<<dim3(HW / 32, CDIM / 32, 2 * BATCH), dim3(32, 8)>>>(t_feat, s_feat);
    k_compact<<<2 * BATCH * NCH, 32>>>();
    k_meanA<<<dim3(2 * BATCH * NCH, 32), 256>>>();
    k_meanB<<<2 * BATCH * NCH, 256>>>();
    k_scale<<<dim3(HW / 8, BATCH, 2), 256>>>();
    k_attn<<<dim3(HW / TGT, NCH - 1, 2 * BATCH), 256, ATTN_SMEM>>>();
    k_fin<<<dim3(HW / 256, NCH - 1, BATCH), 256>>>();
    k_up<<<(BATCH * 3 * HI * HI) / 256, 256>>>(out);
}

// round 6
// speedup vs baseline: 2.1283x; 1.0829x over previous
#include <cuda_runtime.h>
#include <math.h>

#define BATCH 2
#define NCH   8
#define HI    256
#define HS    64
#define HW    4096
#define CDIM  256
#define LOG2E 1.4426950408889634f

typedef unsigned long long ull;

// ---------------- scratch ----------------------------------------------------
__device__ float  g_featT[2][BATCH][HW][CDIM];   // raw transposed features
__device__ float4 g_colP[2][BATCH][HW];
__device__ int    g_lab[2][BATCH][HW];
__device__ int    g_list[2][BATCH][NCH][HW];
__device__ int    g_cnt[2][BATCH][NCH];
__device__ float  g_meanP[2][BATCH][NCH][32][CDIM];
__device__ float  g_mean[2][BATCH][NCH][CDIM];
__device__ float4 g_part[2][BATCH][NCH][HW];     // per-half (x,y,z,l) partials
__device__ float  g_canvas[BATCH][3][HW];

__device__ __forceinline__ void fma2(ull &d, ull a, ull b) {
    asm("fma.rn.f32x2 %0, %1, %2, %0;" : "+l"(d) : "l"(a), "l"(b));
}
__device__ __forceinline__ float2 unpk(ull v) {
    float2 r; asm("mov.b64 {%0,%1}, %2;" : "=f"(r.x), "=f"(r.y) : "l"(v)); return r;
}
__device__ __forceinline__ float ex2(float x) {
    float r; asm("ex2.approx.f32 %0, %1;" : "=f"(r) : "f"(x)); return r;
}

// ---------------- K1: labels, colors, zero canvas ----------------------------
__global__ void k_pre(const float* __restrict__ toh, const float* __restrict__ soh,
                      const float* __restrict__ trgb, const float* __restrict__ srgb)
{
    int pix = blockIdx.x * blockDim.x + threadIdx.x;
    int b = blockIdx.y;
    if (pix >= HW) return;
    int y = pix >> 6, x = pix & 63;
    int y4 = y * 4, x4 = x * 4;
    int tl = 0, sl = 0;
#pragma unroll
    for (int ch = 0; ch < NCH; ch++) {
        size_t o = ((size_t)(b * NCH + ch) * HI + y4) * HI + x4;
        if (toh[o] > 0.f) tl = ch;
        if (soh[o] > 0.f) sl = ch;
    }
    g_lab[0][b][pix] = tl;
    g_lab[1][b][pix] = sl;
    float tc[3], sc[3];
#pragma unroll
    for (int ch = 0; ch < 3; ch++) {
        size_t base = ((size_t)(b * 3 + ch) * HI + (y4 + 1)) * HI + (x4 + 1);
        tc[ch] = 0.25f * (trgb[base] + trgb[base + 1] + trgb[base + HI] + trgb[base + HI + 1]);
        sc[ch] = 0.25f * (srgb[base] + srgb[base + 1] + srgb[base + HI] + srgb[base + HI + 1]);
    }
    g_colP[0][b][pix] = make_float4(tc[0], tc[1], tc[2], 0.f);
    g_colP[1][b][pix] = make_float4(sc[0], sc[1], sc[2], 0.f);
    g_canvas[b][0][pix] = 0.f;
    g_canvas[b][1][pix] = 0.f;
    g_canvas[b][2][pix] = 0.f;
}

// ---------------- K2: transpose [b][ch][pix] -> [side][b][pix][ch] -----------
__global__ void k_transpose(const float* __restrict__ tfeat, const float* __restrict__ sfeat)
{
    __shared__ float tile[32][33];
    int side = blockIdx.z >> 1;
    int b    = blockIdx.z & 1;
    const float* in = side ? sfeat : tfeat;
    int pix0 = blockIdx.x * 32, ch0 = blockIdx.y * 32;
    int tx = threadIdx.x, ty = threadIdx.y;  // (32, 8)
#pragma unroll
    for (int i = 0; i < 32; i += 8)
        tile[ty + i][tx] = in[((size_t)(b * CDIM + ch0 + ty + i)) * HW + pix0 + tx];
    __syncthreads();
#pragma unroll
    for (int i = 0; i < 32; i += 8)
        g_featT[side][b][pix0 + ty + i][ch0 + tx] = tile[tx][ty + i];
}

// ---------------- K3: per-class compaction (order-preserving) ----------------
__global__ void k_compact()
{
    int id = blockIdx.x;              // side*16 + b*8 + cls
    int cls = id & 7, b = (id >> 3) & 1, side = id >> 4;
    int lane = threadIdx.x;
    const int4* __restrict__ lp = (const int4*)g_lab[side][b];
    int* __restrict__ lst = g_list[side][b][cls];
    int base = 0;
    for (int r = 0; r < HW / 128; r++) {
        int4 v = lp[r * 32 + lane];
        int vv[4] = {v.x, v.y, v.z, v.w};
#pragma unroll
        for (int e = 0; e < 4; e++) {
            bool m = (vv[e] == cls);
            unsigned bal = __ballot_sync(0xffffffffu, m);
            if (m) lst[base + __popc(bal & ((1u << lane) - 1u))] = (r * 32 + lane) * 4 + e;
            base += __popc(bal);
        }
    }
    if (lane == 0) g_cnt[side][b][cls] = base;
}

// ---------------- K4a/K4b: class channel means (two-stage, 32 chunks) --------
__global__ void k_meanA()
{
    int sbc = blockIdx.x;
    int cls = sbc & 7, b = (sbc >> 3) & 1, side = sbc >> 4;
    int ck = blockIdx.y, ch = threadIdx.x;
    int n = g_cnt[side][b][cls];
    int lo = (n * ck) >> 5, hi = (n * (ck + 1)) >> 5;
    const int* __restrict__ lst = g_list[side][b][cls];
    float s = 0.f;
    for (int i = lo; i < hi; i++)
        s += g_featT[side][b][lst[i]][ch];
    g_meanP[side][b][cls][ck][ch] = s;
}

__global__ void k_meanB()
{
    int sbc = blockIdx.x;
    int cls = sbc & 7, b = (sbc >> 3) & 1, side = sbc >> 4;
    int ch = threadIdx.x;
    int n = g_cnt[side][b][cls];
    float s = 0.f;
#pragma unroll
    for (int ck = 0; ck < 32; ck++)
        s += g_meanP[side][b][cls][ck][ch];
    g_mean[side][b][cls][ch] = s / (float)max(n, 1);
}

// ---------------- K6: attention (4 warps x 8 targets, fused normalization) ---
// Block: 128 threads = 4 warps; warp w: targets 8w..8w+7, lane = source slot.
// blockIdx.z = b*2 + half (2-way source split, exact partial sums).
// Normalization (center + L2, cnt==1 skip) computed inside the smem fills.
// NOTE: fills execute UNCONDITIONALLY with clamped indices so the full-mask
// shuffles never deadlock on tail chunks.
#define TGT 32
#define ST_BYTES (64 * 33 * 16)
#define TT_BYTES (64 * 33 * 16)
#define ATTN_SMEM (ST_BYTES + TT_BYTES + 2048)

__global__ void __launch_bounds__(128) k_attn()
{
    extern __shared__ unsigned char smem_raw[];
    float4 (*ST4)[33] = (float4(*)[33])(smem_raw);
    float4 (*TT4)[33] = (float4(*)[33])(smem_raw + ST_BYTES);
    float* MEANS = (float*)(smem_raw + ST_BYTES + TT_BYTES);
    float* MEANT = MEANS + 256;

    int cls  = blockIdx.y + 1;
    int half = blockIdx.z & 1;
    int b    = blockIdx.z >> 1;
    int nt = g_cnt[0][b][cls];
    int t0 = blockIdx.x * TGT;
    if (t0 >= nt) return;

    int scnt = g_cnt[1][b][cls];
    int srcSide = (scnt < 9) ? 0 : 1;        // use_self branch
    int nsAll = g_cnt[srcSide][b][cls];
    int sLo = (nsAll * half) >> 1;
    int sHi = (nsAll * (half + 1)) >> 1;
    const int* __restrict__ slist = g_list[srcSide][b][cls];
    const int* __restrict__ tlist = g_list[0][b][cls];

    int tid = threadIdx.x, w = tid >> 5, lane = tid & 31;
    int p = tid & 7;

    MEANS[tid]       = g_mean[srcSide][b][cls][tid];
    MEANS[tid + 128] = g_mean[srcSide][b][cls][tid + 128];
    MEANT[tid]       = g_mean[0][b][cls][tid];
    MEANT[tid + 128] = g_mean[0][b][cls][tid + 128];
    __syncthreads();

    // ---- fill TT4: 32 targets, centered + normalized, log2e folded ----------
#pragma unroll
    for (int rr = 0; rr < 2; rr++) {
        int i = (tid >> 3) + 16 * rr;
        int ti = t0 + i;
        bool valid = ti < nt;
        int tp = tlist[valid ? ti : nt - 1];
        const float4* __restrict__ row = (const float4*)g_featT[0][b][tp];
        const float4* __restrict__ mr = (const float4*)MEANT;
        float4 df[8];
        float sq = 0.f;
#pragma unroll
        for (int r = 0; r < 8; r++) {
            int q = p + 8 * r;
            float4 f = row[q], m = mr[q];
            df[r] = make_float4(f.x - m.x, f.y - m.y, f.z - m.z, f.w - m.w);
            sq += df[r].x * df[r].x + df[r].y * df[r].y
                + df[r].z * df[r].z + df[r].w * df[r].w;
        }
        sq += __shfl_xor_sync(0xffffffffu, sq, 1);
        sq += __shfl_xor_sync(0xffffffffu, sq, 2);
        sq += __shfl_xor_sync(0xffffffffu, sq, 4);
        float sc = !valid ? 0.f
                 : (nt == 1) ? LOG2E : LOG2E / fmaxf(sqrtf(sq), 1e-12f);
#pragma unroll
        for (int r = 0; r < 8; r++) {
            int q = p + 8 * r;
            TT4[q][i] = make_float4(df[r].x * sc, df[r].y * sc,
                                    df[r].z * sc, df[r].w * sc);
        }
    }

    float lv[8], xv[8], yv[8], zv[8];
#pragma unroll
    for (int t = 0; t < 8; t++) { lv[t] = 0.f; xv[t] = 0.f; yv[t] = 0.f; zv[t] = 0.f; }

    for (int c0 = sLo; c0 < sHi; c0 += 32) {
        int n = min(32, sHi - c0);
        __syncthreads();                     // TT ready / prev chunk consumed
        // ---- fill ST4: 32 sources, centered + normalized (no divergence) ----
#pragma unroll
        for (int rr = 0; rr < 2; rr++) {
            int j = (tid >> 3) + 16 * rr;
            int si = min(c0 + j, nsAll - 1);     // clamp padding slots
            int sp = slist[si];
            const float4* __restrict__ row = (const float4*)g_featT[srcSide][b][sp];
            const float4* __restrict__ mr = (const float4*)MEANS;
            float4 df[8];
            float sq = 0.f;
#pragma unroll
            for (int r = 0; r < 8; r++) {
                int q = p + 8 * r;
                float4 f = row[q], m = mr[q];
                df[r] = make_float4(f.x - m.x, f.y - m.y, f.z - m.z, f.w - m.w);
                sq += df[r].x * df[r].x + df[r].y * df[r].y
                    + df[r].z * df[r].z + df[r].w * df[r].w;
            }
            sq += __shfl_xor_sync(0xffffffffu, sq, 1);
            sq += __shfl_xor_sync(0xffffffffu, sq, 2);
            sq += __shfl_xor_sync(0xffffffffu, sq, 4);
            float sc = (nsAll == 1) ? 1.f : 1.f / fmaxf(sqrtf(sq), 1e-12f);
#pragma unroll
            for (int r = 0; r < 8; r++) {
                int q = p + 8 * r;
                ST4[q][j] = make_float4(df[r].x * sc, df[r].y * sc,
                                        df[r].z * sc, df[r].w * sc);
            }
        }
        __syncthreads();

        bool on = lane < n;
        float4 scol = on ? g_colP[srcSide][b][slist[c0 + lane]]
                         : make_float4(0.f, 0.f, 0.f, 0.f);

        ull d[8];
#pragma unroll
        for (int t = 0; t < 8; t++) d[t] = 0;
#pragma unroll 2
        for (int k4 = 0; k4 < 64; k4++) {
            ulonglong2 s = *(const ulonglong2*)&ST4[k4][lane];
#pragma unroll
            for (int t = 0; t < 8; t++) {
                ulonglong2 tv = *(const ulonglong2*)&TT4[k4][8 * w + t];
                fma2(d[t], s.x, tv.x);
                fma2(d[t], s.y, tv.y);
            }
        }
#pragma unroll
        for (int t = 0; t < 8; t++) {
            float2 e = unpk(d[t]);
            float pp = on ? ex2(e.x + e.y) : 0.f;
            lv[t] += pp;
            xv[t] += pp * scol.x;
            yv[t] += pp * scol.y;
            zv[t] += pp * scol.z;
        }
    }

    // per-warp butterfly reduce + write partials
#pragma unroll
    for (int t = 0; t < 8; t++) {
        float l = lv[t], x = xv[t], y = yv[t], z = zv[t];
#pragma unroll
        for (int off = 16; off; off >>= 1) {
            l += __shfl_xor_sync(0xffffffffu, l, off);
            x += __shfl_xor_sync(0xffffffffu, x, off);
            y += __shfl_xor_sync(0xffffffffu, y, off);
            z += __shfl_xor_sync(0xffffffffu, z, off);
        }
        int ti = t0 + 8 * w + t;
        if (lane == 0 && ti < nt)
            g_part[half][b][cls][ti] = make_float4(x, y, z, l);
    }
}

// ---------------- K6b: combine partials, divide, scatter to canvas -----------
__global__ void k_fin()
{
    int cls = blockIdx.y + 1, b = blockIdx.z;
    int ti = blockIdx.x * blockDim.x + threadIdx.x;
    int nt = g_cnt[0][b][cls];
    if (ti >= nt) return;
    float4 pa = g_part[0][b][cls][ti];
    float4 pb = g_part[1][b][cls][ti];
    float l = pa.w + pb.w;
    float inv = 1.f / l;
    int tp = g_list[0][b][cls][ti];
    g_canvas[b][0][tp] = (pa.x + pb.x) * inv;
    g_canvas[b][1][tp] = (pa.y + pb.y) * inv;
    g_canvas[b][2][tp] = (pa.z + pb.z) * inv;
}

// ---------------- K7: bilinear 64->256 upsample + clip -----------------------
__global__ void k_up(float* __restrict__ out)
{
    int idx = blockIdx.x * blockDim.x + threadIdx.x;
    if (idx >= BATCH * 3 * HI * HI) return;
    int ox = idx & 255;
    int oy = (idx >> 8) & 255;
    int bc = idx >> 16;
    int c = bc % 3, b = bc / 3;
    float sy = oy * 0.25f - 0.375f;
    float sx = ox * 0.25f - 0.375f;
    int iy = (int)floorf(sy), ix = (int)floorf(sx);
    float wy = sy - (float)iy, wx = sx - (float)ix;
    int ya = max(iy, 0), yb = min(iy + 1, HS - 1);
    int xa = max(ix, 0), xb = min(ix + 1, HS - 1);
    const float* __restrict__ P = g_canvas[b][c];
    float v00 = P[ya * HS + xa], v01 = P[ya * HS + xb];
    float v10 = P[yb * HS + xa], v11 = P[yb * HS + xb];
    float v = (1.f - wy) * ((1.f - wx) * v00 + wx * v01)
            +        wy  * ((1.f - wx) * v10 + wx * v11);
    out[idx] = fminf(fmaxf(v, -1.f), 1.f);
}

// ---------------- launch -----------------------------------------------------
extern "C" void kernel_launch(void* const* d_in, const int* in_sizes, int n_in,
                              void* d_out, int out_size)
{
    const float* src_rgb = (const float*)d_in[0];
    const float* tgt_rgb = (const float*)d_in[1];
    const float* src_oh  = (const float*)d_in[2];
    const float* tgt_oh  = (const float*)d_in[3];
    const float* t_feat  = (const float*)d_in[4];
    const float* s_feat  = (const float*)d_in[5];
    float* out = (float*)d_out;

    cudaFuncSetAttribute(k_attn, cudaFuncAttributeMaxDynamicSharedMemorySize, ATTN_SMEM);

    k_pre<<<dim3(HW / 256, BATCH), 256>>>(tgt_oh, src_oh, tgt_rgb, src_rgb);
    k_transpose<<<dim3(HW / 32, CDIM / 32, 2 * BATCH), dim3(32, 8)>>>(t_feat, s_feat);
    k_compact<<<2 * BATCH * NCH, 32>>>();
    k_meanA<<<dim3(2 * BATCH * NCH, 32), 256>>>();
    k_meanB<<<2 * BATCH * NCH, 256>>>();
    k_attn<<<dim3(HW / TGT, NCH - 1, 2 * BATCH), 128, ATTN_SMEM>>>();
    k_fin<<<dim3(HW / 256, NCH - 1, BATCH), 256>>>();
    k_up<<<(BATCH * 3 * HI * HI) / 256, 256>>>(out);
}

// round 7
// speedup vs baseline: 2.1970x; 1.0323x over previous
#include <cuda_runtime.h>
#include <math.h>

#define BATCH 2
#define NCH   8
#define HI    256
#define HS    64
#define HW    4096
#define CDIM  256
#define LOG2E 1.4426950408889634f

typedef unsigned long long ull;

// ---------------- scratch ----------------------------------------------------
__device__ float  g_normc[2][BATCH][HW][CDIM];   // normalized, class-compacted
__device__ float4 g_colP[2][BATCH][HW];          // colors by pixel
__device__ float4 g_colc[2][BATCH][HW];          // colors compacted
__device__ int    g_lab[2][BATCH][HW];
__device__ int    g_slot[2][BATCH][HW];          // local slot within class
__device__ int    g_list[2][BATCH][NCH][HW];     // pixel list per class
__device__ int    g_cnt[2][BATCH][NCH];
__device__ int    g_off[2][BATCH][NCH];          // class prefix offsets
__device__ float  g_mean[2][BATCH][NCH][CDIM];
__device__ float4 g_part[2][BATCH][NCH][HW];     // per-half (x,y,z,l) partials
__device__ float  g_canvas[BATCH][3][HW];

__device__ __forceinline__ void fma2(ull &d, ull a, ull b) {
    asm("fma.rn.f32x2 %0, %1, %2, %0;" : "+l"(d) : "l"(a), "l"(b));
}
__device__ __forceinline__ float2 unpk(ull v) {
    float2 r; asm("mov.b64 {%0,%1}, %2;" : "=f"(r.x), "=f"(r.y) : "l"(v)); return r;
}
__device__ __forceinline__ float ex2(float x) {
    float r; asm("ex2.approx.f32 %0, %1;" : "=f"(r) : "f"(x)); return r;
}

// ---------------- K1: labels, colors, zero canvas ----------------------------
__global__ void k_pre(const float* __restrict__ toh, const float* __restrict__ soh,
                      const float* __restrict__ trgb, const float* __restrict__ srgb)
{
    int pix = blockIdx.x * blockDim.x + threadIdx.x;
    int b = blockIdx.y;
    if (pix >= HW) return;
    int y = pix >> 6, x = pix & 63;
    int y4 = y * 4, x4 = x * 4;
    int tl = 0, sl = 0;
#pragma unroll
    for (int ch = 0; ch < NCH; ch++) {
        size_t o = ((size_t)(b * NCH + ch) * HI + y4) * HI + x4;
        if (toh[o] > 0.f) tl = ch;
        if (soh[o] > 0.f) sl = ch;
    }
    g_lab[0][b][pix] = tl;
    g_lab[1][b][pix] = sl;
    float tc[3], sc[3];
#pragma unroll
    for (int ch = 0; ch < 3; ch++) {
        size_t base = ((size_t)(b * 3 + ch) * HI + (y4 + 1)) * HI + (x4 + 1);
        tc[ch] = 0.25f * (trgb[base] + trgb[base + 1] + trgb[base + HI] + trgb[base + HI + 1]);
        sc[ch] = 0.25f * (srgb[base] + srgb[base + 1] + srgb[base + HI] + srgb[base + HI + 1]);
    }
    g_colP[0][b][pix] = make_float4(tc[0], tc[1], tc[2], 0.f);
    g_colP[1][b][pix] = make_float4(sc[0], sc[1], sc[2], 0.f);
    g_canvas[b][0][pix] = 0.f;
    g_canvas[b][1][pix] = 0.f;
    g_canvas[b][2][pix] = 0.f;
}

// ---------------- K2: compaction: lists, slots, counts, prefix offsets -------
__global__ void k_compact()
{
    __shared__ int cnt_sm[NCH];
    int side = blockIdx.x >> 1, b = blockIdx.x & 1;
    int cls = threadIdx.x >> 5, lane = threadIdx.x & 31;
    const int4* __restrict__ lp = (const int4*)g_lab[side][b];
    int* __restrict__ lst = g_list[side][b][cls];
    int* __restrict__ slt = g_slot[side][b];
    int base = 0;
    for (int r = 0; r < HW / 128; r++) {
        int4 v = lp[r * 32 + lane];
        int vv[4] = {v.x, v.y, v.z, v.w};
#pragma unroll
        for (int e = 0; e < 4; e++) {
            bool m = (vv[e] == cls);
            unsigned bal = __ballot_sync(0xffffffffu, m);
            if (m) {
                int s = base + __popc(bal & ((1u << lane) - 1u));
                int p = (r * 32 + lane) * 4 + e;
                lst[s] = p;
                slt[p] = s;
            }
            base += __popc(bal);
        }
    }
    if (lane == 0) { g_cnt[side][b][cls] = base; cnt_sm[cls] = base; }
    __syncthreads();
    if (threadIdx.x == 0) {
        int off = 0;
#pragma unroll
        for (int c = 0; c < NCH; c++) { g_off[side][b][c] = off; off += cnt_sm[c]; }
    }
}

// ---------------- K3: per-class channel means (original layout, predicated) --
__global__ void k_mean(const float* __restrict__ tfeat, const float* __restrict__ sfeat)
{
    __shared__ int lab_sm[HW];
    int b = blockIdx.y, side = blockIdx.z;
    const float* __restrict__ in = side ? sfeat : tfeat;
    int tid = threadIdx.x;
    for (int i = tid; i < HW / 4; i += 256)
        ((int4*)lab_sm)[i] = ((const int4*)g_lab[side][b])[i];
    __syncthreads();
    int ch = blockIdx.x * 8 + (tid >> 5);
    int lane = tid & 31;
    const float4* __restrict__ row = (const float4*)(in + ((size_t)b * CDIM + ch) * HW);
    float acc[7];
#pragma unroll
    for (int c = 0; c < 7; c++) acc[c] = 0.f;
    for (int it = 0; it < HW / 128; it++) {
        int i4 = it * 32 + lane;
        float4 v = row[i4];
        int4 lb = ((const int4*)lab_sm)[i4];
        float vv[4] = {v.x, v.y, v.z, v.w};
        int ll[4] = {lb.x, lb.y, lb.z, lb.w};
#pragma unroll
        for (int e = 0; e < 4; e++)
#pragma unroll
            for (int c = 0; c < 7; c++)
                acc[c] += (ll[e] == c + 1) ? vv[e] : 0.f;
    }
#pragma unroll
    for (int c = 0; c < 7; c++) {
        float s = acc[c];
#pragma unroll
        for (int off = 16; off; off >>= 1) s += __shfl_xor_sync(0xffffffffu, s, off);
        if (lane == 0)
            g_mean[side][b][c + 1][ch] = s / (float)max(g_cnt[side][b][c + 1], 1);
    }
}

// ---------------- K4: fused transpose + center + normalize + compact ---------
// Block: 256 threads, 32 pixels x 256 channels per block.
__global__ void k_tn(const float* __restrict__ tfeat, const float* __restrict__ sfeat)
{
    __shared__ float T[CDIM][33];      // ~33.8 KB
    __shared__ float MS[NCH][257];     // ~8.2 KB class means (class 0 = zeros)
    __shared__ int LB[32], SL[32], OFF[NCH], CNTS[NCH];

    int b = blockIdx.y, side = blockIdx.z;
    int pix0 = blockIdx.x * 32;
    const float* __restrict__ in = side ? sfeat : tfeat;
    int tid = threadIdx.x;

#pragma unroll
    for (int c = 0; c < NCH; c++)
        MS[c][tid] = (c >= 1) ? g_mean[side][b][c][tid] : 0.f;
    if (tid < 32) {
        LB[tid] = g_lab[side][b][pix0 + tid];
        SL[tid] = g_slot[side][b][pix0 + tid];
    }
    if (tid < NCH) {
        OFF[tid] = g_off[side][b][tid];
        CNTS[tid] = g_cnt[side][b][tid];
    }

    // load tile [256 ch][32 px], coalesced
    int px = tid & 31, cg = tid >> 5;
#pragma unroll
    for (int r = 0; r < 32; r++) {
        int ch = cg * 32 + r;
        T[ch][px] = in[((size_t)b * CDIM + ch) * HW + pix0 + px];
    }
    __syncthreads();

    // compacted colors (OFF now valid)
    if (tid < 32 && LB[tid] > 0)
        g_colc[side][b][OFF[LB[tid]] + SL[tid]] = g_colP[side][b][pix0 + tid];

    // center + sumsq: 8 threads per pixel
    int px2 = tid >> 3, p = tid & 7;
    int lab = LB[px2];
    float sq = 0.f;
#pragma unroll
    for (int r = 0; r < 32; r++) {
        int ch = p + 8 * r;
        float d = T[ch][px2] - MS[lab][ch];
        T[ch][px2] = d;
        sq += d * d;
    }
    sq += __shfl_xor_sync(0xffffffffu, sq, 1);
    sq += __shfl_xor_sync(0xffffffffu, sq, 2);
    sq += __shfl_xor_sync(0xffffffffu, sq, 4);
    float scale = (CNTS[lab] == 1) ? 1.f : 1.f / fmaxf(sqrtf(sq), 1e-12f);
    int slotg = OFF[lab] + SL[px2];
    __syncthreads();

    // coalesced compacted write (skip class 0)
    if (lab > 0) {
        float4* __restrict__ orow = (float4*)g_normc[side][b][slotg];
#pragma unroll
        for (int r = 0; r < 8; r++) {
            int q = p + 8 * r;
            float4 v = make_float4(T[4 * q][px2] * scale, T[4 * q + 1][px2] * scale,
                                   T[4 * q + 2][px2] * scale, T[4 * q + 3][px2] * scale);
            orow[q] = v;
        }
    }
}

// ---------------- K5: attention (4 warps x 16 targets, pure-copy fills) ------
#define TGTB 64
#define TPW  16
#define ST_BYTES (64 * 33 * 16)
#define TT_BYTES (64 * 67 * 16)
#define ATTN_SMEM (ST_BYTES + TT_BYTES + 512)

__global__ void __launch_bounds__(128) k_attn()
{
    extern __shared__ unsigned char smem_raw[];
    float4 (*ST4)[33] = (float4(*)[33])(smem_raw);
    float4 (*TT4)[67] = (float4(*)[67])(smem_raw + ST_BYTES);
    float4* SC = (float4*)(smem_raw + ST_BYTES + TT_BYTES);

    int cls  = blockIdx.y + 1;
    int half = blockIdx.z & 1;
    int b    = blockIdx.z >> 1;
    int nt = g_cnt[0][b][cls];
    int t0 = blockIdx.x * TGTB;
    if (t0 >= nt) return;

    int scnt = g_cnt[1][b][cls];
    int srcSide = (scnt < 9) ? 0 : 1;
    int nsAll = g_cnt[srcSide][b][cls];
    int sLo = (nsAll * half) >> 1;
    int sHi = (nsAll * (half + 1)) >> 1;

    const float4* __restrict__ tFeat = (const float4*)g_normc[0][b][g_off[0][b][cls]];
    const float4* __restrict__ sFeat = (const float4*)g_normc[srcSide][b][g_off[srcSide][b][cls]];
    const float4* __restrict__ sCol  = &g_colc[srcSide][b][g_off[srcSide][b][cls]];

    int tid = threadIdx.x, w = tid >> 5, lane = tid & 31;

    // TT fill: 64 targets x 64 float4, LOG2E folded
#pragma unroll
    for (int k = 0; k < 32; k++) {
        int idx = tid + 128 * k;
        int row = idx >> 6, q = idx & 63;
        int ti = min(t0 + row, nt - 1);
        float4 f = tFeat[ti * 64 + q];
        TT4[q][row] = make_float4(f.x * LOG2E, f.y * LOG2E, f.z * LOG2E, f.w * LOG2E);
    }

    float lv[TPW], xv[TPW], yv[TPW], zv[TPW];
#pragma unroll
    for (int t = 0; t < TPW; t++) { lv[t] = 0.f; xv[t] = 0.f; yv[t] = 0.f; zv[t] = 0.f; }

    for (int c0 = sLo; c0 < sHi; c0 += 32) {
        int n = min(32, sHi - c0);
        __syncthreads();                 // TT ready / prev chunk consumed
        // ST fill: 32 sources x 64 float4, pure copy
#pragma unroll
        for (int k = 0; k < 16; k++) {
            int idx = tid + 128 * k;
            int row = idx >> 6, q = idx & 63;
            int si = min(c0 + row, sHi - 1);
            ST4[q][row] = sFeat[si * 64 + q];
        }
        if (tid < 32) SC[tid] = sCol[min(c0 + tid, sHi - 1)];
        __syncthreads();

        bool on = lane < n;
        float4 scol = SC[lane];

        ull d[TPW];
#pragma unroll
        for (int t = 0; t < TPW; t++) d[t] = 0;
#pragma unroll 2
        for (int k4 = 0; k4 < 64; k4++) {
            ulonglong2 s = *(const ulonglong2*)&ST4[k4][lane];
#pragma unroll
            for (int t = 0; t < TPW; t++) {
                ulonglong2 tv = *(const ulonglong2*)&TT4[k4][TPW * w + t];
                fma2(d[t], s.x, tv.x);
                fma2(d[t], s.y, tv.y);
            }
        }
#pragma unroll
        for (int t = 0; t < TPW; t++) {
            float2 e = unpk(d[t]);
            float pp = on ? ex2(e.x + e.y) : 0.f;
            lv[t] += pp;
            xv[t] += pp * scol.x;
            yv[t] += pp * scol.y;
            zv[t] += pp * scol.z;
        }
    }

#pragma unroll
    for (int t = 0; t < TPW; t++) {
        float l = lv[t], x = xv[t], y = yv[t], z = zv[t];
#pragma unroll
        for (int off = 16; off; off >>= 1) {
            l += __shfl_xor_sync(0xffffffffu, l, off);
            x += __shfl_xor_sync(0xffffffffu, x, off);
            y += __shfl_xor_sync(0xffffffffu, y, off);
            z += __shfl_xor_sync(0xffffffffu, z, off);
        }
        int ti = t0 + TPW * w + t;
        if (lane == 0 && ti < nt)
            g_part[half][b][cls][ti] = make_float4(x, y, z, l);
    }
}

// ---------------- K6: combine partials, divide, scatter ----------------------
__global__ void k_fin()
{
    int cls = blockIdx.y + 1, b = blockIdx.z;
    int ti = blockIdx.x * blockDim.x + threadIdx.x;
    int nt = g_cnt[0][b][cls];
    if (ti >= nt) return;
    float4 pa = g_part[0][b][cls][ti];
    float4 pb = g_part[1][b][cls][ti];
    float inv = 1.f / (pa.w + pb.w);
    int tp = g_list[0][b][cls][ti];
    g_canvas[b][0][tp] = (pa.x + pb.x) * inv;
    g_canvas[b][1][tp] = (pa.y + pb.y) * inv;
    g_canvas[b][2][tp] = (pa.z + pb.z) * inv;
}

// ---------------- K7: bilinear 64->256 upsample + clip -----------------------
__global__ void k_up(float* __restrict__ out)
{
    int idx = blockIdx.x * blockDim.x + threadIdx.x;
    if (idx >= BATCH * 3 * HI * HI) return;
    int ox = idx & 255;
    int oy = (idx >> 8) & 255;
    int bc = idx >> 16;
    int c = bc % 3, b = bc / 3;
    float sy = oy * 0.25f - 0.375f;
    float sx = ox * 0.25f - 0.375f;
    int iy = (int)floorf(sy), ix = (int)floorf(sx);
    float wy = sy - (float)iy, wx = sx - (float)ix;
    int ya = max(iy, 0), yb = min(iy + 1, HS - 1);
    int xa = max(ix, 0), xb = min(ix + 1, HS - 1);
    const float* __restrict__ P = g_canvas[b][c];
    float v00 = P[ya * HS + xa], v01 = P[ya * HS + xb];
    float v10 = P[yb * HS + xa], v11 = P[yb * HS + xb];
    float v = (1.f - wy) * ((1.f - wx) * v00 + wx * v01)
            +        wy  * ((1.f - wx) * v10 + wx * v11);
    out[idx] = fminf(fmaxf(v, -1.f), 1.f);
}

// ---------------- launch -----------------------------------------------------
extern "C" void kernel_launch(void* const* d_in, const int* in_sizes, int n_in,
                              void* d_out, int out_size)
{
    const float* src_rgb = (const float*)d_in[0];
    const float* tgt_rgb = (const float*)d_in[1];
    const float* src_oh  = (const float*)d_in[2];
    const float* tgt_oh  = (const float*)d_in[3];
    const float* t_feat  = (const float*)d_in[4];
    const float* s_feat  = (const float*)d_in[5];
    float* out = (float*)d_out;

    cudaFuncSetAttribute(k_attn, cudaFuncAttributeMaxDynamicSharedMemorySize, ATTN_SMEM);

    k_pre<<<dim3(HW / 256, BATCH), 256>>>(tgt_oh, src_oh, tgt_rgb, src_rgb);
    k_compact<<<2 * BATCH, 256>>>();
    k_mean<<<dim3(CDIM / 8, BATCH, 2), 256>>>(t_feat, s_feat);
    k_tn<<<dim3(HW / 32, BATCH, 2), 256>>>(t_feat, s_feat);
    k_attn<<<dim3(HW / TGTB, NCH - 1, 2 * BATCH), 128, ATTN_SMEM>>>();
    k_fin<<<dim3(HW / 256, NCH - 1, BATCH), 256>>>();
    k_up<<<(BATCH * 3 * HI * HI) / 256, 256>>>(out);
}